// round 2
// baseline (speedup 1.0000x reference)
#include <cuda_runtime.h>
#include <math.h>

#define B_DIM 1024
#define T_DIM 256
#define C_DIM 512
#define H_DIM 64
#define MROWS (B_DIM * T_DIM)   // 262144

typedef unsigned long long ull;

// Packed f32x2 helpers (sm_103a FFMA2 path — only reachable via PTX).
__device__ __forceinline__ ull fma2(ull a, ull b, ull c) {
    ull d;
    asm("fma.rn.f32x2 %0, %1, %2, %3;" : "=l"(d) : "l"(a), "l"(b), "l"(c));
    return d;
}
__device__ __forceinline__ float hsum2(ull v) {
    float lo, hi;
    asm("mov.b64 {%0,%1}, %2;" : "=f"(lo), "=f"(hi) : "l"(v));
    return lo + hi;
}

// Scratch for projected Q, K, V (64 MB each) — __device__ globals, no allocation.
__device__ float g_q[MROWS * H_DIM];
__device__ float g_k[MROWS * H_DIM];
__device__ float g_v[MROWS * H_DIM];

// ---------------------------------------------------------------------------
// Kernel 1: QKV projection.  Y = X @ W,  X:[M,512] row-major, W:[512,64].
// Tile BM=128, BN=64, BK=32; 256 threads; 8m x 4n micro-tile; K-paired FFMA2.
// As:[m][k] (k contig, stride 36), Bs transposed:[n][k] (stride 34).
// grid=(3, M/128): blockIdx.x selects {Wq,Wk,Wv} fastest -> L2 reuse of X.
// ---------------------------------------------------------------------------
#define PBM 128
#define PBK 32
#define PBN 64
#define ASTR 36   // 32 + 4 pad; multiple of 4 (float4 STS align), even (LDS.64)
#define BSTR 34   // even for LDS.64; row stride 34 -> bank stride 2 (conflict-free)

__global__ __launch_bounds__(256) void proj_kernel(
    const float* __restrict__ x,
    const float* __restrict__ Wq,
    const float* __restrict__ Wk,
    const float* __restrict__ Wv)
{
    __shared__ __align__(16) float As[PBM * ASTR];
    __shared__ __align__(16) float Bs[PBN * BSTR];

    const int which = blockIdx.x;
    const float* __restrict__ W = (which == 0) ? Wq : (which == 1) ? Wk : Wv;
    float* __restrict__ Y = (which == 0) ? g_q : (which == 1) ? g_k : g_v;

    const int mbase = blockIdx.y * PBM;
    const int tid = threadIdx.x;
    const int m0 = (tid >> 4) << 3;   // 16 row-groups of 8
    const int n0 = tid & 15;          // cols n0 + 16*j, j<4 (bank-friendly)

    ull acc[8][4];
#pragma unroll
    for (int i = 0; i < 8; ++i)
#pragma unroll
        for (int j = 0; j < 4; ++j) acc[i][j] = 0ULL;

    for (int k0 = 0; k0 < C_DIM; k0 += PBK) {
        // A tile: 128 x 32 floats = 1024 float4, 4 per thread, coalesced.
#pragma unroll
        for (int s = 0; s < 4; ++s) {
            int f = tid + s * 256;
            int arow = f >> 3;
            int ac4 = f & 7;
            float4 v4 = *reinterpret_cast<const float4*>(
                &x[(size_t)(mbase + arow) * C_DIM + k0 + ac4 * 4]);
            *reinterpret_cast<float4*>(&As[arow * ASTR + ac4 * 4]) = v4;
        }
        // B tile: 32 x 64 floats read coalesced, stored transposed [n][k].
#pragma unroll
        for (int s = 0; s < 2; ++s) {
            int f = tid + s * 256;
            int kr = f >> 4;
            int nc4 = f & 15;
            float4 w4 = *reinterpret_cast<const float4*>(
                &W[(size_t)(k0 + kr) * H_DIM + nc4 * 4]);
            Bs[(nc4 * 4 + 0) * BSTR + kr] = w4.x;
            Bs[(nc4 * 4 + 1) * BSTR + kr] = w4.y;
            Bs[(nc4 * 4 + 2) * BSTR + kr] = w4.z;
            Bs[(nc4 * 4 + 3) * BSTR + kr] = w4.w;
        }
        __syncthreads();

#pragma unroll
        for (int kp = 0; kp < PBK / 2; ++kp) {
            const int kk = kp * 2;
            ull a2[8], b2[4];
#pragma unroll
            for (int i = 0; i < 8; ++i)
                a2[i] = *reinterpret_cast<const ull*>(&As[(m0 + i) * ASTR + kk]);
#pragma unroll
            for (int j = 0; j < 4; ++j)
                b2[j] = *reinterpret_cast<const ull*>(&Bs[(n0 + 16 * j) * BSTR + kk]);
#pragma unroll
            for (int i = 0; i < 8; ++i)
#pragma unroll
                for (int j = 0; j < 4; ++j)
                    acc[i][j] = fma2(a2[i], b2[j], acc[i][j]);
        }
        __syncthreads();
    }

#pragma unroll
    for (int i = 0; i < 8; ++i)
#pragma unroll
        for (int j = 0; j < 4; ++j)
            Y[(size_t)(mbase + m0 + i) * H_DIM + n0 + 16 * j] = hsum2(acc[i][j]);
}

// ---------------------------------------------------------------------------
// Kernel 2: causal attention, one 512-thread CTA per batch. K-paired FFMA2.
//   Ks: [256][66]  K rows, k contig (stride 66 -> bank stride 2, LDS.64-clean)
//   Vt: [64][258]  V TRANSPOSED [head][token] so GEMM2 pairs over token dim
//   S : [64][260]  scores / probabilities (k contig for GEMM2 a-loads)
//   Qt: [64][68]   query tile
// 4 query tiles of 64 rows; causal structure skips key tiles beyond diagonal.
// ---------------------------------------------------------------------------
#define KS_STR 66
#define VT_STR 258
#define S_STR 260
#define QT_STR 68
#define SMEM_FLOATS (T_DIM * KS_STR + H_DIM * VT_STR + 64 * S_STR + 64 * QT_STR)
// = 16896 + 16512 + 16640 + 4352 = 54400 floats = 217600 bytes

extern __shared__ float sm_dyn[];

__global__ __launch_bounds__(512) void attn_kernel(float* __restrict__ out)
{
    float* Ks = sm_dyn;
    float* Vt = Ks + T_DIM * KS_STR;
    float* S  = Vt + H_DIM * VT_STR;
    float* Qt = S + 64 * S_STR;
    __shared__ float rowsum[64];

    const int b = blockIdx.x;
    const int tid = threadIdx.x;
    const int lane = tid & 31;
    const int wid = tid >> 5;          // 0..15
    const size_t base = (size_t)b * T_DIM * H_DIM;

    // Stage K (k-contig rows, stride 66) and V transposed [h][token].
    for (int f = tid; f < (T_DIM * H_DIM) / 4; f += 512) {   // 4096 float4 each
        int j = f >> 4;          // token
        int h4 = f & 15;         // head-chunk
        float4 kv = *reinterpret_cast<const float4*>(&g_k[base + (size_t)j * H_DIM + h4 * 4]);
        float* d = &Ks[j * KS_STR + h4 * 4];
        d[0] = kv.x; d[1] = kv.y; d[2] = kv.z; d[3] = kv.w;
        float4 vv = *reinterpret_cast<const float4*>(&g_v[base + (size_t)j * H_DIM + h4 * 4]);
        Vt[(h4 * 4 + 0) * VT_STR + j] = vv.x;
        Vt[(h4 * 4 + 1) * VT_STR + j] = vv.y;
        Vt[(h4 * 4 + 2) * VT_STR + j] = vv.z;
        Vt[(h4 * 4 + 3) * VT_STR + j] = vv.w;
    }
    __syncthreads();

    // GEMM1 map: 16 warps = 8 row-groups x 2 col-halves.
    const int m0a = (wid >> 1) << 3;   // 8 query rows per warp
    const int ch = wid & 1;            // column half: n = ch*32 + lane + 64*j
    // GEMM2 map: rows (tid>>4)*2, cols tid&15 + 16*j.
    const int m0b = (tid >> 4) << 1;
    const int n0b = tid & 15;
    // softmax: 8 threads per row
    const int r_s = tid >> 3;
    const int sub = tid & 7;

    for (int qt = 0; qt < 4; ++qt) {
        // Stage Q tile (64 x 64) float4 into stride-68 rows.
        for (int f = tid; f < (64 * H_DIM) / 4; f += 512) {
            int r = f >> 4;
            int h4 = f & 15;
            float4 qv = *reinterpret_cast<const float4*>(
                &g_q[base + (size_t)(qt * 64 + r) * H_DIM + h4 * 4]);
            *reinterpret_cast<float4*>(&Qt[r * QT_STR + h4 * 4]) = qv;
        }
        __syncthreads();

        // ---- GEMM1: S = Qt @ Ks^T, K-paired FFMA2 ----
        const int jlim = qt + 1;       // n = ch*32+lane+64j valid while j <= qt
        ull acc1[8][4];
#pragma unroll
        for (int i = 0; i < 8; ++i)
#pragma unroll
            for (int j = 0; j < 4; ++j) acc1[i][j] = 0ULL;

#pragma unroll 8
        for (int kp = 0; kp < H_DIM / 2; ++kp) {
            const int kk = kp * 2;
            ull a2[8], b2[4];
#pragma unroll
            for (int i = 0; i < 8; ++i)
                a2[i] = *reinterpret_cast<const ull*>(&Qt[(m0a + i) * QT_STR + kk]);
#pragma unroll
            for (int j = 0; j < 4; ++j) {
                if (j < jlim)
                    b2[j] = *reinterpret_cast<const ull*>(
                        &Ks[(ch * 32 + lane + 64 * j) * KS_STR + kk]);
            }
#pragma unroll
            for (int j = 0; j < 4; ++j) {
                if (j < jlim)
#pragma unroll
                    for (int i = 0; i < 8; ++i)
                        acc1[i][j] = fma2(a2[i], b2[j], acc1[i][j]);
            }
        }
#pragma unroll
        for (int j = 0; j < 4; ++j) {
            if (j < jlim) {
#pragma unroll
                for (int i = 0; i < 8; ++i)
                    S[(m0a + i) * S_STR + ch * 32 + lane + 64 * j] = hsum2(acc1[i][j]);
            }
        }
        __syncthreads();

        // ---- Softmax: scale + causal mask, 8 threads per row ----
        {
            const int qrow = qt * 64 + r_s;
            const int ilim = (qt + 1) * 8;   // j = sub + 8*i covers [0, 64*(qt+1))
            float m = -1e30f;
            for (int i = 0; i < ilim; ++i) {
                int j = sub + 8 * i;
                if (j <= qrow) m = fmaxf(m, S[r_s * S_STR + j]);
            }
            m = fmaxf(m, __shfl_xor_sync(0xffffffffu, m, 1));
            m = fmaxf(m, __shfl_xor_sync(0xffffffffu, m, 2));
            m = fmaxf(m, __shfl_xor_sync(0xffffffffu, m, 4));

            float l = 0.0f;
            for (int i = 0; i < ilim; ++i) {
                int j = sub + 8 * i;
                float p = 0.0f;
                if (j <= qrow) {
                    float v = S[r_s * S_STR + j];
                    p = __expf((v - m) * 0.125f);   // scale = H^-0.5 = 1/8
                }
                S[r_s * S_STR + j] = p;
                l += p;
            }
            l += __shfl_xor_sync(0xffffffffu, l, 1);
            l += __shfl_xor_sync(0xffffffffu, l, 2);
            l += __shfl_xor_sync(0xffffffffu, l, 4);
            if (sub == 0) rowsum[r_s] = l;
        }
        __syncthreads();

        // ---- GEMM2: O = P @ V, token-paired FFMA2 against transposed Vt ----
        const int kplim = (qt + 1) * 32;   // token pairs
        ull acc2[2][4];
#pragma unroll
        for (int i = 0; i < 2; ++i)
#pragma unroll
            for (int j = 0; j < 4; ++j) acc2[i][j] = 0ULL;

#pragma unroll 4
        for (int kp = 0; kp < kplim; ++kp) {
            const int kk = kp * 2;
            ull a2[2], b2[4];
#pragma unroll
            for (int i = 0; i < 2; ++i)
                a2[i] = *reinterpret_cast<const ull*>(&S[(m0b + i) * S_STR + kk]);
#pragma unroll
            for (int j = 0; j < 4; ++j)
                b2[j] = *reinterpret_cast<const ull*>(&Vt[(n0b + 16 * j) * VT_STR + kk]);
#pragma unroll
            for (int i = 0; i < 2; ++i)
#pragma unroll
                for (int j = 0; j < 4; ++j)
                    acc2[i][j] = fma2(a2[i], b2[j], acc2[i][j]);
        }

#pragma unroll
        for (int i = 0; i < 2; ++i) {
            float inv = 1.0f / rowsum[m0b + i];
#pragma unroll
            for (int j = 0; j < 4; ++j)
                out[base + (size_t)(qt * 64 + m0b + i) * H_DIM + n0b + 16 * j] =
                    hsum2(acc2[i][j]) * inv;
        }
        __syncthreads();   // S/Qt reused next tile
    }
}

// ---------------------------------------------------------------------------
extern "C" void kernel_launch(void* const* d_in, const int* in_sizes, int n_in,
                              void* d_out, int out_size)
{
    const float* x  = (const float*)d_in[0];
    const float* Wq = (const float*)d_in[1];
    const float* Wk = (const float*)d_in[2];
    const float* Wv = (const float*)d_in[3];
    float* out = (float*)d_out;

    (void)in_sizes; (void)n_in; (void)out_size;

    cudaFuncSetAttribute(attn_kernel,
                         cudaFuncAttributeMaxDynamicSharedMemorySize,
                         SMEM_FLOATS * (int)sizeof(float));

    dim3 pgrid(3, MROWS / PBM, 1);
    proj_kernel<<<pgrid, 256>>>(x, Wq, Wk, Wv);

    attn_kernel<<<B_DIM, 512, SMEM_FLOATS * sizeof(float)>>>(out);
}

// round 7
// speedup vs baseline: 2.2194x; 2.2194x over previous
#include <cuda_runtime.h>
#include <cuda_bf16.h>
#include <cstdint>
#include <math.h>

#define B_DIM 1024
#define T_DIM 256
#define C_DIM 512
#define H_DIM 64
#define MROWS (B_DIM * T_DIM)   // 262144

typedef unsigned long long ull;

// ---------------- packed f32x2 helpers (attn kernel) ----------------
__device__ __forceinline__ ull fma2(ull a, ull b, ull c) {
    ull d;
    asm("fma.rn.f32x2 %0, %1, %2, %3;" : "=l"(d) : "l"(a), "l"(b), "l"(c));
    return d;
}
__device__ __forceinline__ float hsum2(ull v) {
    float lo, hi;
    asm("mov.b64 {%0,%1}, %2;" : "=f"(lo), "=f"(hi) : "l"(v));
    return lo + hi;
}

// ---------------- scratch (device globals; no allocation) ----------------
__device__ float g_q[MROWS * H_DIM];
__device__ float g_k[MROWS * H_DIM];
__device__ float g_v[MROWS * H_DIM];
// Split W, bf16: [w:3][hi/lo:2][n:64][k:512]
__device__ __align__(16) uint16_t g_ws[3 * 2 * 64 * 512];

// ---------------- mma.sync / ldmatrix / cp.async helpers ----------------
__device__ __forceinline__ uint32_t smem_u32(const void* p) {
    uint32_t a;
    asm("{ .reg .u64 t; cvta.to.shared.u64 t, %1; cvt.u32.u64 %0, t; }" : "=r"(a) : "l"(p));
    return a;
}
__device__ __forceinline__ void ldsm4(uint32_t* r, uint32_t addr) {
    asm volatile("ldmatrix.sync.aligned.m8n8.x4.shared.b16 {%0,%1,%2,%3}, [%4];"
                 : "=r"(r[0]), "=r"(r[1]), "=r"(r[2]), "=r"(r[3]) : "r"(addr));
}
__device__ __forceinline__ void mma16816(float* c, const uint32_t* a, uint32_t b0, uint32_t b1) {
    asm volatile("mma.sync.aligned.m16n8k16.row.col.f32.bf16.bf16.f32 "
                 "{%0,%1,%2,%3}, {%4,%5,%6,%7}, {%8,%9}, {%0,%1,%2,%3};"
                 : "+f"(c[0]), "+f"(c[1]), "+f"(c[2]), "+f"(c[3])
                 : "r"(a[0]), "r"(a[1]), "r"(a[2]), "r"(a[3]), "r"(b0), "r"(b1));
}
__device__ __forceinline__ void cpasync16(uint32_t smem, const void* gptr) {
    asm volatile("cp.async.ca.shared.global [%0], [%1], 16;"
                 :: "r"(smem), "l"(__cvta_generic_to_global(gptr)) : "memory");
}
__device__ __forceinline__ void cpasync_commit() {
    asm volatile("cp.async.commit_group;" ::: "memory");
}
__device__ __forceinline__ void cpasync_wait0() {
    asm volatile("cp.async.wait_group 0;" ::: "memory");
}
__device__ __forceinline__ uint16_t f2bf_rn(float f) {
    uint32_t b = __float_as_uint(f);
    uint32_t r = b + 0x7FFFu + ((b >> 16) & 1u);
    return (uint16_t)(r >> 16);
}

// One dynamic-smem symbol for all kernels.
extern __shared__ unsigned char dynsm[];

// ---------------------------------------------------------------------------
// Kernel 0: split fp32 W into (hi-truncate, lo-rn) bf16, layout [w][h/l][n][k].
// ---------------------------------------------------------------------------
__global__ void prep_w(const float* __restrict__ Wq,
                       const float* __restrict__ Wk,
                       const float* __restrict__ Wv)
{
    int idx = blockIdx.x * 256 + threadIdx.x;        // 3*512*64 = 98304
    if (idx >= 3 * C_DIM * H_DIM) return;
    int w = idx >> 15;
    int k = (idx >> 6) & 511;
    int n = idx & 63;
    const float* W = (w == 0) ? Wq : (w == 1) ? Wk : Wv;
    float v = W[k * H_DIM + n];
    uint32_t vb = __float_as_uint(v);
    uint16_t hib = (uint16_t)(vb >> 16);                      // truncation hi
    float hif = __uint_as_float(vb & 0xFFFF0000u);
    uint16_t lob = f2bf_rn(v - hif);                          // rn lo (exact diff)
    g_ws[((size_t)(w * 2 + 0) * 64 + n) * 512 + k] = hib;
    g_ws[((size_t)(w * 2 + 1) * 64 + n) * 512 + k] = lob;
}

// ---------------------------------------------------------------------------
// Kernel 1: QKV projection via mma.sync bf16 (fp32 accum), compensated split:
//   Y = Xh*Wh + Xh*Wl + Xl*Wh.
// Per CTA: 128 rows, 64 cols x 3 W, K = 8 chunks of 64. 256 threads, 8 warps,
// each warp owns 16 rows. Double-buffered: W via cp.async, X via reg staging.
// smem (bytes): Abuf[2] @ {0, 36864}: hi(18432 = 128 rows x 144B) | lo(+18432)
//               Wbuf[2] @ {73728, 129024}: 6 mats x 9216 (64 rows x 144B)
// 144B row pad -> ldmatrix conflict-free (144/4 = 36 = 4 mod 32 banks).
// ---------------------------------------------------------------------------
#define A_OFF(b) ((uint32_t)(b) * 36864u)
#define A_LO 18432u
#define W_OFF(b) (73728u + (uint32_t)(b) * 55296u)
#define PROJ_SMEM 184320

__global__ __launch_bounds__(256) void proj_kernel(const float* __restrict__ x)
{
    unsigned char* sm = dynsm;
    const uint32_t smb = smem_u32(sm);
    const int tid = threadIdx.x;
    const int wid = tid >> 5;
    const int lane = tid & 31;
    const int mbase = blockIdx.x * 128;

    // ldmatrix lane addressing
    const uint32_t arow = (uint32_t)(wid * 16 + (lane & 15));
    const uint32_t akhalf = (uint32_t)((lane >> 4) << 4);      // bytes
    const uint32_t bn_loc = (uint32_t)((lane & 7) + ((lane >> 4) << 3));
    const uint32_t bkoff = (uint32_t)(((lane >> 3) & 1) << 4); // bytes

    float acc[3][8][4];
#pragma unroll
    for (int w = 0; w < 3; ++w)
#pragma unroll
        for (int j = 0; j < 8; ++j)
#pragma unroll
            for (int t = 0; t < 4; ++t) acc[w][j][t] = 0.0f;

    float4 xr[8];

    // ---- prologue: chunk 0 ----
    {
#pragma unroll
        for (int i = 0; i < 12; ++i) {
            int idx = tid + i * 256;               // 0..3071
            int mi = idx >> 9;                     // 0..5
            int n = (idx >> 3) & 63;
            int seg = idx & 7;
            const uint16_t* src = &g_ws[((size_t)(mi * 64 + n) * 512) + 0 * 64 + seg * 8];
            cpasync16(smb + W_OFF(0) + (uint32_t)(mi * 9216 + n * 144 + seg * 16), src);
        }
        cpasync_commit();
#pragma unroll
        for (int i = 0; i < 8; ++i) {
            int f = tid + i * 256;                 // 0..2047
            int row = f >> 4, c4 = f & 15;
            xr[i] = *reinterpret_cast<const float4*>(
                &x[(size_t)(mbase + row) * C_DIM + 0 * 64 + c4 * 4]);
        }
#pragma unroll
        for (int i = 0; i < 8; ++i) {
            int f = tid + i * 256;
            int row = f >> 4, c4 = f & 15;
            uint32_t b0 = __float_as_uint(xr[i].x), b1 = __float_as_uint(xr[i].y);
            uint32_t b2 = __float_as_uint(xr[i].z), b3 = __float_as_uint(xr[i].w);
            uint32_t hi01 = (b0 >> 16) | (b1 & 0xFFFF0000u);
            uint32_t hi23 = (b2 >> 16) | (b3 & 0xFFFF0000u);
            float l0 = xr[i].x - __uint_as_float(b0 & 0xFFFF0000u);
            float l1 = xr[i].y - __uint_as_float(b1 & 0xFFFF0000u);
            float l2 = xr[i].z - __uint_as_float(b2 & 0xFFFF0000u);
            float l3 = xr[i].w - __uint_as_float(b3 & 0xFFFF0000u);
            uint32_t lo01 = (uint32_t)f2bf_rn(l0) | ((uint32_t)f2bf_rn(l1) << 16);
            uint32_t lo23 = (uint32_t)f2bf_rn(l2) | ((uint32_t)f2bf_rn(l3) << 16);
            uint32_t off = (uint32_t)(row * 144 + c4 * 8);
            *(ull*)(sm + A_OFF(0) + off)        = (ull)hi01 | ((ull)hi23 << 32);
            *(ull*)(sm + A_OFF(0) + A_LO + off) = (ull)lo01 | ((ull)lo23 << 32);
        }
    }

    for (int c = 0; c < 8; ++c) {
        const int cb = c & 1;
        cpasync_wait0();            // W[c] landed
        __syncthreads();            // A[c] stores visible to all warps

        if (c < 7) {
            // prefetch W[c+1]
#pragma unroll
            for (int i = 0; i < 12; ++i) {
                int idx = tid + i * 256;
                int mi = idx >> 9;
                int n = (idx >> 3) & 63;
                int seg = idx & 7;
                const uint16_t* src =
                    &g_ws[((size_t)(mi * 64 + n) * 512) + (c + 1) * 64 + seg * 8];
                cpasync16(smb + W_OFF(cb ^ 1) + (uint32_t)(mi * 9216 + n * 144 + seg * 16), src);
            }
            cpasync_commit();
            // prefetch X[c+1] into regs
#pragma unroll
            for (int i = 0; i < 8; ++i) {
                int f = tid + i * 256;
                int row = f >> 4, c4 = f & 15;
                xr[i] = *reinterpret_cast<const float4*>(
                    &x[(size_t)(mbase + row) * C_DIM + (c + 1) * 64 + c4 * 4]);
            }
        }

        // ---- MMA over chunk c ----
        const uint32_t ah_base = smb + A_OFF(cb) + arow * 144 + akhalf;
        const uint32_t al_base = ah_base + A_LO;
        const uint32_t wbase = smb + W_OFF(cb);
#pragma unroll
        for (int s = 0; s < 4; ++s) {
            const uint32_t kb = (uint32_t)(s * 32);   // k16 step = 32 bytes
            uint32_t ah[4], al[4];
            ldsm4(ah, ah_base + kb);
            ldsm4(al, al_base + kb);
#pragma unroll
            for (int w = 0; w < 3; ++w) {
#pragma unroll
                for (int nt = 0; nt < 4; ++nt) {
                    const uint32_t brow = (uint32_t)(nt * 16) + bn_loc;
                    uint32_t bh[4], bl[4];
                    ldsm4(bh, wbase + (uint32_t)((w * 2 + 0) * 9216) + brow * 144 + kb + bkoff);
                    ldsm4(bl, wbase + (uint32_t)((w * 2 + 1) * 9216) + brow * 144 + kb + bkoff);
                    mma16816(acc[w][2 * nt],     ah, bh[0], bh[1]);
                    mma16816(acc[w][2 * nt + 1], ah, bh[2], bh[3]);
                    mma16816(acc[w][2 * nt],     ah, bl[0], bl[1]);
                    mma16816(acc[w][2 * nt + 1], ah, bl[2], bl[3]);
                    mma16816(acc[w][2 * nt],     al, bh[0], bh[1]);
                    mma16816(acc[w][2 * nt + 1], al, bh[2], bh[3]);
                }
            }
        }

        // convert staged X[c+1] into the other A buffer
        if (c < 7) {
#pragma unroll
            for (int i = 0; i < 8; ++i) {
                int f = tid + i * 256;
                int row = f >> 4, c4 = f & 15;
                uint32_t b0 = __float_as_uint(xr[i].x), b1 = __float_as_uint(xr[i].y);
                uint32_t b2 = __float_as_uint(xr[i].z), b3 = __float_as_uint(xr[i].w);
                uint32_t hi01 = (b0 >> 16) | (b1 & 0xFFFF0000u);
                uint32_t hi23 = (b2 >> 16) | (b3 & 0xFFFF0000u);
                float l0 = xr[i].x - __uint_as_float(b0 & 0xFFFF0000u);
                float l1 = xr[i].y - __uint_as_float(b1 & 0xFFFF0000u);
                float l2 = xr[i].z - __uint_as_float(b2 & 0xFFFF0000u);
                float l3 = xr[i].w - __uint_as_float(b3 & 0xFFFF0000u);
                uint32_t lo01 = (uint32_t)f2bf_rn(l0) | ((uint32_t)f2bf_rn(l1) << 16);
                uint32_t lo23 = (uint32_t)f2bf_rn(l2) | ((uint32_t)f2bf_rn(l3) << 16);
                uint32_t off = (uint32_t)(row * 144 + c4 * 8);
                *(ull*)(sm + A_OFF(cb ^ 1) + off)        = (ull)hi01 | ((ull)hi23 << 32);
                *(ull*)(sm + A_OFF(cb ^ 1) + A_LO + off) = (ull)lo01 | ((ull)lo23 << 32);
            }
        }
    }

    // ---- epilogue: C-frag -> fp32 QKV ----
    const int row0 = mbase + wid * 16 + (lane >> 2);
#pragma unroll
    for (int w = 0; w < 3; ++w) {
        float* dst = (w == 0) ? g_q : (w == 1) ? g_k : g_v;
#pragma unroll
        for (int j = 0; j < 8; ++j) {
            const int col = j * 8 + 2 * (lane & 3);
            float2 v01 = { acc[w][j][0], acc[w][j][1] };
            float2 v23 = { acc[w][j][2], acc[w][j][3] };
            *reinterpret_cast<float2*>(&dst[(size_t)row0 * H_DIM + col]) = v01;
            *reinterpret_cast<float2*>(&dst[(size_t)(row0 + 8) * H_DIM + col]) = v23;
        }
    }
}

// ---------------------------------------------------------------------------
// Kernel 2: causal attention (unchanged; measured 451us).
// ---------------------------------------------------------------------------
#define KS_STR 66
#define VT_STR 258
#define S_STR 260
#define QT_STR 68
#define ATTN_SMEM_FLOATS (T_DIM * KS_STR + H_DIM * VT_STR + 64 * S_STR + 64 * QT_STR)
// 217600 bytes

__global__ __launch_bounds__(512) void attn_kernel(float* __restrict__ out)
{
    float* sm_dyn = reinterpret_cast<float*>(dynsm);
    float* Ks = sm_dyn;
    float* Vt = Ks + T_DIM * KS_STR;
    float* S  = Vt + H_DIM * VT_STR;
    float* Qt = S + 64 * S_STR;
    __shared__ float rowsum[64];

    const int b = blockIdx.x;
    const int tid = threadIdx.x;
    const int lane = tid & 31;
    const int wid = tid >> 5;
    const size_t base = (size_t)b * T_DIM * H_DIM;

    for (int f = tid; f < (T_DIM * H_DIM) / 4; f += 512) {
        int j = f >> 4;
        int h4 = f & 15;
        float4 kv = *reinterpret_cast<const float4*>(&g_k[base + (size_t)j * H_DIM + h4 * 4]);
        float* d = &Ks[j * KS_STR + h4 * 4];
        d[0] = kv.x; d[1] = kv.y; d[2] = kv.z; d[3] = kv.w;
        float4 vv = *reinterpret_cast<const float4*>(&g_v[base + (size_t)j * H_DIM + h4 * 4]);
        Vt[(h4 * 4 + 0) * VT_STR + j] = vv.x;
        Vt[(h4 * 4 + 1) * VT_STR + j] = vv.y;
        Vt[(h4 * 4 + 2) * VT_STR + j] = vv.z;
        Vt[(h4 * 4 + 3) * VT_STR + j] = vv.w;
    }
    __syncthreads();

    const int m0a = (wid >> 1) << 3;
    const int ch = wid & 1;
    const int m0b = (tid >> 4) << 1;
    const int n0b = tid & 15;
    const int r_s = tid >> 3;
    const int sub = tid & 7;

    for (int qt = 0; qt < 4; ++qt) {
        for (int f = tid; f < (64 * H_DIM) / 4; f += 512) {
            int r = f >> 4;
            int h4 = f & 15;
            float4 qv = *reinterpret_cast<const float4*>(
                &g_q[base + (size_t)(qt * 64 + r) * H_DIM + h4 * 4]);
            *reinterpret_cast<float4*>(&Qt[r * QT_STR + h4 * 4]) = qv;
        }
        __syncthreads();

        const int jlim = qt + 1;
        ull acc1[8][4];
#pragma unroll
        for (int i = 0; i < 8; ++i)
#pragma unroll
            for (int j = 0; j < 4; ++j) acc1[i][j] = 0ULL;

#pragma unroll 8
        for (int kp = 0; kp < H_DIM / 2; ++kp) {
            const int kk = kp * 2;
            ull a2[8], b2[4];
#pragma unroll
            for (int i = 0; i < 8; ++i)
                a2[i] = *reinterpret_cast<const ull*>(&Qt[(m0a + i) * QT_STR + kk]);
#pragma unroll
            for (int j = 0; j < 4; ++j) {
                if (j < jlim)
                    b2[j] = *reinterpret_cast<const ull*>(
                        &Ks[(ch * 32 + lane + 64 * j) * KS_STR + kk]);
            }
#pragma unroll
            for (int j = 0; j < 4; ++j) {
                if (j < jlim)
#pragma unroll
                    for (int i = 0; i < 8; ++i)
                        acc1[i][j] = fma2(a2[i], b2[j], acc1[i][j]);
            }
        }
#pragma unroll
        for (int j = 0; j < 4; ++j) {
            if (j < jlim) {
#pragma unroll
                for (int i = 0; i < 8; ++i)
                    S[(m0a + i) * S_STR + ch * 32 + lane + 64 * j] = hsum2(acc1[i][j]);
            }
        }
        __syncthreads();

        {
            const int qrow = qt * 64 + r_s;
            const int ilim = (qt + 1) * 8;
            float m = -1e30f;
            for (int i = 0; i < ilim; ++i) {
                int j = sub + 8 * i;
                if (j <= qrow) m = fmaxf(m, S[r_s * S_STR + j]);
            }
            m = fmaxf(m, __shfl_xor_sync(0xffffffffu, m, 1));
            m = fmaxf(m, __shfl_xor_sync(0xffffffffu, m, 2));
            m = fmaxf(m, __shfl_xor_sync(0xffffffffu, m, 4));

            float l = 0.0f;
            for (int i = 0; i < ilim; ++i) {
                int j = sub + 8 * i;
                float p = 0.0f;
                if (j <= qrow) {
                    float v = S[r_s * S_STR + j];
                    p = __expf((v - m) * 0.125f);
                }
                S[r_s * S_STR + j] = p;
                l += p;
            }
            l += __shfl_xor_sync(0xffffffffu, l, 1);
            l += __shfl_xor_sync(0xffffffffu, l, 2);
            l += __shfl_xor_sync(0xffffffffu, l, 4);
            if (sub == 0) rowsum[r_s] = l;
        }
        __syncthreads();

        const int kplim = (qt + 1) * 32;
        ull acc2[2][4];
#pragma unroll
        for (int i = 0; i < 2; ++i)
#pragma unroll
            for (int j = 0; j < 4; ++j) acc2[i][j] = 0ULL;

#pragma unroll 4
        for (int kp = 0; kp < kplim; ++kp) {
            const int kk = kp * 2;
            ull a2[2], b2[4];
#pragma unroll
            for (int i = 0; i < 2; ++i)
                a2[i] = *reinterpret_cast<const ull*>(&S[(m0b + i) * S_STR + kk]);
#pragma unroll
            for (int j = 0; j < 4; ++j)
                b2[j] = *reinterpret_cast<const ull*>(&Vt[(n0b + 16 * j) * VT_STR + kk]);
#pragma unroll
            for (int i = 0; i < 2; ++i)
#pragma unroll
                for (int j = 0; j < 4; ++j)
                    acc2[i][j] = fma2(a2[i], b2[j], acc2[i][j]);
        }

#pragma unroll
        for (int i = 0; i < 2; ++i) {
            float inv = 1.0f / rowsum[m0b + i];
#pragma unroll
            for (int j = 0; j < 4; ++j)
                out[base + (size_t)(qt * 64 + m0b + i) * H_DIM + n0b + 16 * j] =
                    hsum2(acc2[i][j]) * inv;
        }
        __syncthreads();
    }
}

// ---------------------------------------------------------------------------
extern "C" void kernel_launch(void* const* d_in, const int* in_sizes, int n_in,
                              void* d_out, int out_size)
{
    const float* x  = (const float*)d_in[0];
    const float* Wq = (const float*)d_in[1];
    const float* Wk = (const float*)d_in[2];
    const float* Wv = (const float*)d_in[3];
    float* out = (float*)d_out;

    (void)in_sizes; (void)n_in; (void)out_size;

    cudaFuncSetAttribute(proj_kernel,
                         cudaFuncAttributeMaxDynamicSharedMemorySize, PROJ_SMEM);
    cudaFuncSetAttribute(attn_kernel,
                         cudaFuncAttributeMaxDynamicSharedMemorySize,
                         ATTN_SMEM_FLOATS * (int)sizeof(float));

    prep_w<<<384, 256>>>(Wq, Wk, Wv);
    proj_kernel<<<MROWS / 128, 256, PROJ_SMEM>>>(x);
    attn_kernel<<<B_DIM, 512, ATTN_SMEM_FLOATS * sizeof(float)>>>(out);
}